// round 5
// baseline (speedup 1.0000x reference)
#include <cuda_runtime.h>
#include <cuda_bf16.h>
#include <cstdint>

// ---------------- problem constants ----------------
#define WIN     400
#define HOP     100
#define PADL    300
#define T_IN    480000
#define BATCH   32
#define C_OUT   514
#define F_OUT   4803

// GEMM rows: 512 = C_OUT minus the two zero-structure channels (257, 513),
// which are computed by a separate exact scalar kernel.
#define MROWS   512
#define KREAL   400               // 6 chunks of 64 + 1 chunk of 16
#define NCHUNK  7
#define XPAD    486784            // 300 zeros + signal + tail zeros

#define TILE_M  128
#define TILE_N  128
#define NT_C    4
#define NT_F    38
#define THREADS 512

// ---------------- device scratch ----------------
__device__ __nv_bfloat16 g_wh[MROWS * KREAL];
__device__ __nv_bfloat16 g_wl[MROWS * KREAL];
__device__ __nv_bfloat16 g_xh[BATCH * (size_t)XPAD];
__device__ __nv_bfloat16 g_xl[BATCH * (size_t)XPAD];

// ---------------- smem layout ----------------
#define PITCH_B     144                        // 64 bf16 + 16B pad per row
#define SPLIT_BYTES (128 * PITCH_B)            // 18432
#define STAGE_BYTES (2 * SPLIT_BYTES)
#define OFF_A(s)    ((s) * STAGE_BYTES)
#define OFF_B(s)    (73728 + (s) * STAGE_BYTES)
#define SMEM_TOTAL  147456
#define EPI_PITCH   129

// ---------------- helpers ----------------
__device__ __forceinline__ uint32_t smem_u32(const void* p) {
    uint32_t a;
    asm("{ .reg .u64 t; cvta.to.shared.u64 t, %1; cvt.u32.u64 %0, t; }" : "=r"(a) : "l"(p));
    return a;
}
__device__ __forceinline__ void cp16(uint32_t dst, const void* src) {
    asm volatile("cp.async.cg.shared.global [%0], [%1], 16;" :: "r"(dst), "l"(src));
}
__device__ __forceinline__ void cp8(uint32_t dst, const void* src) {
    asm volatile("cp.async.ca.shared.global [%0], [%1], 8;" :: "r"(dst), "l"(src));
}
__device__ __forceinline__ void cp_commit() {
    asm volatile("cp.async.commit_group;" ::: "memory");
}
template <int N>
__device__ __forceinline__ void cp_wait() {
    asm volatile("cp.async.wait_group %0;" :: "n"(N) : "memory");
}
__device__ __forceinline__ void ldsm_x4(uint32_t& r0, uint32_t& r1, uint32_t& r2, uint32_t& r3,
                                        uint32_t addr) {
    asm volatile("ldmatrix.sync.aligned.m8n8.x4.shared.b16 {%0,%1,%2,%3}, [%4];"
                 : "=r"(r0), "=r"(r1), "=r"(r2), "=r"(r3) : "r"(addr));
}
__device__ __forceinline__ void mma16816(float* d, const uint32_t* a, const uint32_t* b) {
    asm volatile(
        "mma.sync.aligned.m16n8k16.row.col.f32.bf16.bf16.f32 "
        "{%0,%1,%2,%3}, {%4,%5,%6,%7}, {%8,%9}, {%0,%1,%2,%3};"
        : "+f"(d[0]), "+f"(d[1]), "+f"(d[2]), "+f"(d[3])
        : "r"(a[0]), "r"(a[1]), "r"(a[2]), "r"(a[3]), "r"(b[0]), "r"(b[1]));
}

// ---------------- prep kernels ----------------
// GEMM row r maps to output channel c = r + (r >= 257): skips channels 257, 513.
__global__ void prep_w_kernel(const float* __restrict__ w) {
    int idx = blockIdx.x * blockDim.x + threadIdx.x;
    if (idx >= MROWS * KREAL) return;
    int r = idx / KREAL;
    int k = idx - r * KREAL;
    int c = r + (r >= 257);
    float v = w[c * KREAL + k];
    __nv_bfloat16 h = __float2bfloat16(v);
    g_wh[idx] = h;
    g_wl[idx] = __float2bfloat16(v - __bfloat162float(h));
}

__global__ void prep_x_kernel(const float* __restrict__ x) {
    size_t idx = (size_t)blockIdx.x * blockDim.x + threadIdx.x;
    if (idx >= (size_t)BATCH * XPAD) return;
    int b = (int)(idx / XPAD);
    int i = (int)(idx - (size_t)b * XPAD);
    int src = i - PADL;
    float v = (src >= 0 && src < T_IN) ? x[(size_t)b * T_IN + src] : 0.0f;
    __nv_bfloat16 h = __float2bfloat16(v);
    g_xh[idx] = h;
    g_xl[idx] = __float2bfloat16(v - __bfloat162float(h));
}

// ---------------- exact scalar conv for the 2 skipped channels ----------------
#define ZSEG 13100
__global__ void edge_ch_kernel(const float* __restrict__ x,
                               const float* __restrict__ w,
                               float* __restrict__ out)
{
    extern __shared__ float zs[];              // [ZSEG] signal + [WIN] weights
    float* sxs = zs;
    float* sws = zs + ZSEG;
    const int f0 = blockIdx.x * 128;
    const int ch = (blockIdx.y == 0) ? 257 : 513;
    const int b  = blockIdx.z;
    const int tid = threadIdx.x;

    const int base = f0 * HOP - PADL;
    const float* xb = x + (size_t)b * T_IN;
    for (int i = tid; i < ZSEG; i += 128) {
        int gi = base + i;
        sxs[i] = (gi >= 0 && gi < T_IN) ? xb[gi] : 0.0f;
    }
    for (int i = tid; i < WIN; i += 128) sws[i] = w[ch * WIN + i];
    __syncthreads();

    float acc = 0.0f;
    const float* sp = sxs + tid * HOP;
    #pragma unroll 8
    for (int k = 0; k < WIN; k++) acc = fmaf(sp[k], sws[k], acc);

    int f = f0 + tid;
    if (f < F_OUT) out[((size_t)b * C_OUT + ch) * F_OUT + f] = acc;
}

// ---------------- main pipelined HMMA GEMM kernel ----------------
__global__ __launch_bounds__(THREADS, 1)
void conv_stft_hmma_kernel(float* __restrict__ out)
{
    extern __shared__ char smem[];
    const uint32_t sbase = smem_u32(smem);
    const int tid  = threadIdx.x;
    const int wid  = tid >> 5;
    const int lane = tid & 31;

    const int c0 = blockIdx.x * TILE_M;        // GEMM row base (0..384)
    const int f0 = blockIdx.y * TILE_N;
    const int b  = blockIdx.z;

    const char* wh_base = reinterpret_cast<const char*>(g_wh) + (size_t)c0 * KREAL * 2;
    const char* wl_base = reinterpret_cast<const char*>(g_wl) + (size_t)c0 * KREAL * 2;
    const char* xh_base = reinterpret_cast<const char*>(g_xh + (size_t)b * XPAD + f0 * HOP);
    const char* xl_base = reinterpret_cast<const char*>(g_xl + (size_t)b * XPAD + f0 * HOP);

    // stage one K-chunk into double-buffer stage s (chunk 6 is 16-wide)
    auto stage = [&](int kc, int s) {
        const int last = (kc == 6);
        const int sha = last ? 1 : 3;          // log2(16B units per A row)
        const int na  = 2 * TILE_M << sha;
        #pragma unroll 2
        for (int i = tid; i < na; i += THREADS) {
            int per = TILE_M << sha;
            int split = i >= per;
            int j = i - split * per;
            int r = j >> sha, u = j & ((1 << sha) - 1);
            const char* src = (split ? wl_base : wh_base) + r * (KREAL * 2) + kc * 128 + u * 16;
            cp16(sbase + OFF_A(s) + split * SPLIT_BYTES + r * PITCH_B + u * 16, src);
        }
        const int shb = last ? 2 : 4;          // log2(8B units per B row)
        const int nb  = 2 * TILE_N << shb;
        #pragma unroll 2
        for (int i = tid; i < nb; i += THREADS) {
            int per = TILE_N << shb;
            int split = i >= per;
            int j = i - split * per;
            int f = j >> shb, u = j & ((1 << shb) - 1);
            const char* src = (split ? xl_base : xh_base) + f * (HOP * 2) + kc * 128 + u * 8;
            cp8(sbase + OFF_B(s) + split * SPLIT_BYTES + f * PITCH_B + u * 8, src);
        }
        cp_commit();
    };

    // warp tile: 4 (M) x 4 (N), each 32x32
    const int m0 = (wid >> 2) * 32;
    const int n0 = (wid & 3) * 32;

    float acc[2][4][4];
    #pragma unroll
    for (int i = 0; i < 2; i++)
        #pragma unroll
        for (int j = 0; j < 4; j++)
            #pragma unroll
            for (int q = 0; q < 4; q++) acc[i][j][q] = 0.0f;

    const uint32_t a_off = (m0 + (lane & 15)) * PITCH_B + (lane >> 4) * 16;
    const uint32_t b_off = (n0 + ((lane >> 4) << 3) + (lane & 7)) * PITCH_B + ((lane >> 3) & 1) * 16;

    stage(0, 0);

    for (int kc = 0; kc < NCHUNK; kc++) {
        const int s = kc & 1;
        if (kc < NCHUNK - 1) { stage(kc + 1, s ^ 1); cp_wait<1>(); }
        else                 { cp_wait<0>(); }
        __syncthreads();

        const uint32_t ah_base = sbase + OFF_A(s) + a_off;
        const uint32_t al_base = ah_base + SPLIT_BYTES;
        const uint32_t bh_base = sbase + OFF_B(s) + b_off;
        const uint32_t bl_base = bh_base + SPLIT_BYTES;
        const int nks = (kc == 6) ? 1 : 4;

        #pragma unroll 4
        for (int ks = 0; ks < nks; ks++) {
            uint32_t ah[2][4], al[2][4], bh[2][4], bl[2][4];
            #pragma unroll
            for (int mi = 0; mi < 2; mi++) {
                ldsm_x4(ah[mi][0], ah[mi][1], ah[mi][2], ah[mi][3],
                        ah_base + mi * 16 * PITCH_B + ks * 32);
                ldsm_x4(al[mi][0], al[mi][1], al[mi][2], al[mi][3],
                        al_base + mi * 16 * PITCH_B + ks * 32);
            }
            #pragma unroll
            for (int np = 0; np < 2; np++) {
                ldsm_x4(bh[np][0], bh[np][1], bh[np][2], bh[np][3],
                        bh_base + np * 16 * PITCH_B + ks * 32);
                ldsm_x4(bl[np][0], bl[np][1], bl[np][2], bl[np][3],
                        bl_base + np * 16 * PITCH_B + ks * 32);
            }
            #pragma unroll
            for (int mi = 0; mi < 2; mi++)
                #pragma unroll
                for (int ni = 0; ni < 4; ni++) {
                    const uint32_t* bhf = &bh[ni >> 1][(ni & 1) * 2];
                    const uint32_t* blf = &bl[ni >> 1][(ni & 1) * 2];
                    mma16816(acc[mi][ni], ah[mi], bhf);
                    mma16816(acc[mi][ni], ah[mi], blf);
                    mma16816(acc[mi][ni], al[mi], bhf);
                }
        }
        if (kc < NCHUNK - 1) __syncthreads();
    }

    // ---- epilogue: registers -> smem transpose -> coalesced stores ----
    __syncthreads();
    float* epi = reinterpret_cast<float*>(smem);
    const int g = lane >> 2;
    const int t = lane & 3;
    #pragma unroll
    for (int mi = 0; mi < 2; mi++)
        #pragma unroll
        for (int ni = 0; ni < 4; ni++) {
            int col = n0 + ni * 8 + t * 2;
            #pragma unroll
            for (int half = 0; half < 2; half++) {
                int row = m0 + mi * 16 + half * 8 + g;
                epi[row * EPI_PITCH + col]     = acc[mi][ni][half * 2];
                epi[row * EPI_PITCH + col + 1] = acc[mi][ni][half * 2 + 1];
            }
        }
    __syncthreads();

    #pragma unroll 4
    for (int idx = tid; idx < TILE_M * TILE_N; idx += THREADS) {
        int row = idx >> 7;
        int col = idx & 127;
        int R = c0 + row;
        int c = R + (R >= 257);                // skip zero-structure channels
        int f = f0 + col;
        if (f < F_OUT)
            out[((size_t)b * C_OUT + c) * F_OUT + f] = epi[row * EPI_PITCH + col];
    }
}

// ---------------- launcher ----------------
extern "C" void kernel_launch(void* const* d_in, const int* in_sizes, int n_in,
                              void* d_out, int out_size)
{
    const float* x = (const float*)d_in[0];
    const float* w = (const float*)d_in[1];
    float* out = (float*)d_out;

    prep_w_kernel<<<(MROWS * KREAL + 255) / 256, 256>>>(w);
    prep_x_kernel<<<(int)(((size_t)BATCH * XPAD + 255) / 256), 256>>>(x);

    // channels 257 & 513, computed exactly in fp32
    cudaFuncSetAttribute(edge_ch_kernel,
                         cudaFuncAttributeMaxDynamicSharedMemorySize,
                         (ZSEG + WIN) * (int)sizeof(float));
    dim3 zgrid(NT_F, 2, BATCH);
    edge_ch_kernel<<<zgrid, 128, (ZSEG + WIN) * sizeof(float)>>>(x, w, out);

    cudaFuncSetAttribute(conv_stft_hmma_kernel,
                         cudaFuncAttributeMaxDynamicSharedMemorySize, SMEM_TOTAL);
    dim3 grid(NT_C, NT_F, BATCH);   // 4 x 38 x 32 = 4864 CTAs
    conv_stft_hmma_kernel<<<grid, THREADS, SMEM_TOTAL>>>(out);
}